// round 2
// baseline (speedup 1.0000x reference)
#include <cuda_runtime.h>
#include <cstdint>

#define N_VOX 200000
#define CCH   64
#define PP    65536
#define NOFF  26
#define EPSV  1e-5f

// Scratch (allocation-free rule: __device__ globals)
__device__ float g_h1[(size_t)N_VOX * CCH];
__device__ float g_h2[(size_t)N_VOX * CCH];
__device__ float g_stats[256];  // [0:64] sum1 [64:128] sq1 [128:192] sum2 [192:256] sq2
__device__ float g_coef[256];   // [0:64] scale1 [64:128] shift1 [128:192] scale2 [192:256] shift2

#define PACKDUP(d, s) asm("mov.b64 %0, {%1, %1};" : "=l"(d) : "f"(s))
#define FMA2(a, xv, wv) asm("fma.rn.f32x2 %0, %1, %2, %0;" : "+l"(a) : "l"(xv), "l"(wv))
#define UNPACK2(lo, hi, a) asm("mov.b64 {%0, %1}, %2;" : "=f"(lo), "=f"(hi) : "l"(a))
#define RED4(p, a, b, c, d) \
    asm volatile("red.global.add.v4.f32 [%0], {%1,%2,%3,%4};" \
                 :: "l"(p), "f"(a), "f"(b), "f"(c), "f"(d) : "memory")

// ---------------------------------------------------------------------------
// f32x2 conv kernel. Tile = 128 pairs/rows x 64 out channels, 128 threads.
// Thread (cg = t>>4 in 0..7 -> 8 out channels; pg = t&15 -> 4 pair-pairs
// strided by 16) owns 8 pairs x 8 channels = 32 f32x2 accumulators.
// x tile staged TRANSPOSED (sXT[c][pair], stride 128) so LDS.64 gives a
// packed {x[p_even], x[p_odd]} directly. W row (8 ch) dup'd once per c.
// ---------------------------------------------------------------------------
template <bool SCATTER>
__global__ __launch_bounds__(128)
void conv_kernel(const float* __restrict__ x,
                 const float* __restrict__ W,      // [27,64,64]
                 const int*   __restrict__ in_map, // [26,P] or null
                 const int*   __restrict__ out_map,
                 float*       __restrict__ H)
{
    __shared__ float sW[64 * 64];    // 16 KB  sW[c][ch]
    __shared__ float sXT[64 * 128];  // 32 KB  sXT[c][pair]

    const int t = threadIdx.x;
    const int base = blockIdx.x * 128;
    const int k = SCATTER ? blockIdx.y : 0;
    const float* Wk = W + (size_t)(SCATTER ? (k < 13 ? k : k + 1) : 13) * 4096;

    int row;
    if (SCATTER) {
        // sentinels are tail-packed per offset: first-pair sentinel => whole tile dead
        if (__ldg(&in_map[(size_t)k * PP + base]) >= N_VOX) return;
        row = __ldg(&in_map[(size_t)k * PP + base + t]);
    } else {
        row = base + t;
    }

    // Stage W_k (16 KB)
    const float4* W4  = reinterpret_cast<const float4*>(Wk);
    float4*       sW4 = reinterpret_cast<float4*>(sW);
#pragma unroll
    for (int i = 0; i < 8; i++) sW4[t + i * 128] = W4[t + i * 128];

    // Stage row t transposed into sXT[:, t]
    {
        const float4* x4 = reinterpret_cast<const float4*>(x);
        const bool ok = row < N_VOX;
#pragma unroll
        for (int i = 0; i < 16; i++) {
            float4 v = ok ? x4[(size_t)row * 16 + i] : make_float4(0.f, 0.f, 0.f, 0.f);
            sXT[(4 * i + 0) * 128 + t] = v.x;
            sXT[(4 * i + 1) * 128 + t] = v.y;
            sXT[(4 * i + 2) * 128 + t] = v.z;
            sXT[(4 * i + 3) * 128 + t] = v.w;
        }
    }
    __syncthreads();

    const int cg = t >> 4;   // channel group: ch [8cg, 8cg+8)
    const int pg = t & 15;   // pair-pair group: pp = pg + 16j, j=0..3

    unsigned long long acc[4][8];
#pragma unroll
    for (int j = 0; j < 4; j++)
#pragma unroll
        for (int i = 0; i < 8; i++) acc[j][i] = 0ull;

    const unsigned long long* sXT2 =
        reinterpret_cast<const unsigned long long*>(sXT);

#pragma unroll 2
    for (int c = 0; c < 64; c++) {
        float4 w0 = sW4[c * 16 + cg * 2];
        float4 w1 = sW4[c * 16 + cg * 2 + 1];
        unsigned long long wd[8];
        PACKDUP(wd[0], w0.x); PACKDUP(wd[1], w0.y);
        PACKDUP(wd[2], w0.z); PACKDUP(wd[3], w0.w);
        PACKDUP(wd[4], w1.x); PACKDUP(wd[5], w1.y);
        PACKDUP(wd[6], w1.z); PACKDUP(wd[7], w1.w);

        unsigned long long xv[4];
#pragma unroll
        for (int j = 0; j < 4; j++) xv[j] = sXT2[c * 64 + pg + 16 * j];

#pragma unroll
        for (int j = 0; j < 4; j++)
#pragma unroll
            for (int i = 0; i < 8; i++) FMA2(acc[j][i], xv[j], wd[i]);
    }

    // Epilogue
#pragma unroll
    for (int j = 0; j < 4; j++) {
        float lo[8], hi[8];
#pragma unroll
        for (int i = 0; i < 8; i++) UNPACK2(lo[i], hi[i], acc[j][i]);
        const int p0 = 2 * (pg + 16 * j);
        if (SCATTER) {
            int2 om = __ldg(reinterpret_cast<const int2*>(
                &out_map[(size_t)k * PP + base + p0]));
            if (om.x < N_VOX) {
                float* d = H + (size_t)om.x * 64 + cg * 8;
                RED4(d,     lo[0], lo[1], lo[2], lo[3]);
                RED4(d + 4, lo[4], lo[5], lo[6], lo[7]);
            }
            if (om.y < N_VOX) {
                float* d = H + (size_t)om.y * 64 + cg * 8;
                RED4(d,     hi[0], hi[1], hi[2], hi[3]);
                RED4(d + 4, hi[4], hi[5], hi[6], hi[7]);
            }
        } else {
            const int r0 = base + p0;
            float4* H4 = reinterpret_cast<float4*>(H);
            if (r0 < N_VOX) {
                H4[(size_t)r0 * 16 + cg * 2]     = make_float4(lo[0], lo[1], lo[2], lo[3]);
                H4[(size_t)r0 * 16 + cg * 2 + 1] = make_float4(lo[4], lo[5], lo[6], lo[7]);
            }
            if (r0 + 1 < N_VOX) {
                H4[(size_t)(r0 + 1) * 16 + cg * 2]     = make_float4(hi[0], hi[1], hi[2], hi[3]);
                H4[(size_t)(r0 + 1) * 16 + cg * 2 + 1] = make_float4(hi[4], hi[5], hi[6], hi[7]);
            }
        }
    }
}

// ---------------------------------------------------------------------------
__global__ void zero_stats_kernel() { g_stats[threadIdx.x] = 0.f; }

__global__ void stats_kernel(const float* __restrict__ h, int statoff)
{
    const int t  = threadIdx.x;   // 256
    const int c4 = t & 15;        // float4 column (4 channels)
    const int rg = t >> 4;        // 16 rows in parallel
    const float4* h4 = reinterpret_cast<const float4*>(h);
    float4 s = make_float4(0.f, 0.f, 0.f, 0.f);
    float4 q = make_float4(0.f, 0.f, 0.f, 0.f);
#pragma unroll 4
    for (int row = blockIdx.x * 16 + rg; row < N_VOX; row += gridDim.x * 16) {
        float4 v = h4[(size_t)row * 16 + c4];
        s.x += v.x; q.x = fmaf(v.x, v.x, q.x);
        s.y += v.y; q.y = fmaf(v.y, v.y, q.y);
        s.z += v.z; q.z = fmaf(v.z, v.z, q.z);
        s.w += v.w; q.w = fmaf(v.w, v.w, q.w);
    }
    __shared__ float4 sh_s[16][16];
    __shared__ float4 sh_q[16][16];
    sh_s[rg][c4] = s;
    sh_q[rg][c4] = q;
    __syncthreads();
    if (t < 32) {
        const int cc = t & 15;
        const bool isq = t >= 16;
        float4 a = isq ? sh_q[0][cc] : sh_s[0][cc];
#pragma unroll
        for (int r = 1; r < 16; r++) {
            float4 b = isq ? sh_q[r][cc] : sh_s[r][cc];
            a.x += b.x; a.y += b.y; a.z += b.z; a.w += b.w;
        }
        float* dst = &g_stats[statoff + (isq ? 64 : 0) + cc * 4];
        atomicAdd(dst + 0, a.x);
        atomicAdd(dst + 1, a.y);
        atomicAdd(dst + 2, a.z);
        atomicAdd(dst + 3, a.w);
    }
}

__global__ void finalize_stats_kernel(const float* __restrict__ gamma,
                                      const float* __restrict__ beta,
                                      int statoff, int coefoff)
{
    const int c = threadIdx.x;  // 64
    const float inv_n = 1.0f / (float)N_VOX;
    float mu  = g_stats[statoff + c] * inv_n;
    float var = g_stats[statoff + 64 + c] * inv_n - mu * mu;
    float sc  = gamma[c] * rsqrtf(var + EPSV);
    g_coef[coefoff + c]      = sc;
    g_coef[coefoff + 64 + c] = beta[c] - mu * sc;
}

// in-place BN + ReLU on h (float4 granularity)
__global__ void bnrelu_kernel(float* __restrict__ h, int coefoff)
{
    int kk = blockIdx.x * blockDim.x + threadIdx.x;   // float4 index
    if (kk >= N_VOX * 16) return;
    int cb = (kk & 15) * 4;
    float4 v = reinterpret_cast<float4*>(h)[kk];
    float s0 = g_coef[coefoff + cb + 0], b0 = g_coef[coefoff + 64 + cb + 0];
    float s1 = g_coef[coefoff + cb + 1], b1 = g_coef[coefoff + 64 + cb + 1];
    float s2 = g_coef[coefoff + cb + 2], b2 = g_coef[coefoff + 64 + cb + 2];
    float s3 = g_coef[coefoff + cb + 3], b3 = g_coef[coefoff + 64 + cb + 3];
    v.x = fmaxf(fmaf(v.x, s0, b0), 0.f);
    v.y = fmaxf(fmaf(v.y, s1, b1), 0.f);
    v.z = fmaxf(fmaf(v.z, s2, b2), 0.f);
    v.w = fmaxf(fmaf(v.w, s3, b3), 0.f);
    reinterpret_cast<float4*>(h)[kk] = v;
}

// out = relu(bn2(h2) + x)
__global__ void final_kernel(const float* __restrict__ h2,
                             const float* __restrict__ x,
                             float* __restrict__ out, int coefoff)
{
    int kk = blockIdx.x * blockDim.x + threadIdx.x;
    if (kk >= N_VOX * 16) return;
    int cb = (kk & 15) * 4;
    float4 v = reinterpret_cast<const float4*>(h2)[kk];
    float4 r = reinterpret_cast<const float4*>(x)[kk];
    float s0 = g_coef[coefoff + cb + 0], b0 = g_coef[coefoff + 64 + cb + 0];
    float s1 = g_coef[coefoff + cb + 1], b1 = g_coef[coefoff + 64 + cb + 1];
    float s2 = g_coef[coefoff + cb + 2], b2 = g_coef[coefoff + 64 + cb + 2];
    float s3 = g_coef[coefoff + cb + 3], b3 = g_coef[coefoff + 64 + cb + 3];
    v.x = fmaxf(fmaf(v.x, s0, b0) + r.x, 0.f);
    v.y = fmaxf(fmaf(v.y, s1, b1) + r.y, 0.f);
    v.z = fmaxf(fmaf(v.z, s2, b2) + r.z, 0.f);
    v.w = fmaxf(fmaf(v.w, s3, b3) + r.w, 0.f);
    reinterpret_cast<float4*>(out)[kk] = v;
}

// ---------------------------------------------------------------------------
extern "C" void kernel_launch(void* const* d_in, const int* in_sizes, int n_in,
                              void* d_out, int out_size)
{
    const float* x      = (const float*)d_in[0];
    const float* W1     = (const float*)d_in[1];
    const float* gamma1 = (const float*)d_in[2];
    const float* beta1  = (const float*)d_in[3];
    const float* W2     = (const float*)d_in[4];
    const float* gamma2 = (const float*)d_in[5];
    const float* beta2  = (const float*)d_in[6];
    const int*   in_map = (const int*)d_in[7];
    const int*   out_map= (const int*)d_in[8];
    float*       out    = (float*)d_out;

    float* h1;  cudaGetSymbolAddress((void**)&h1, g_h1);
    float* h2;  cudaGetSymbolAddress((void**)&h2, g_h2);

    const dim3 scat_grid(PP / 128, NOFF);
    const int  center_blocks = (N_VOX + 127) / 128;
    const int  ew_blocks     = (N_VOX * 16 + 255) / 256;

    zero_stats_kernel<<<1, 256>>>();

    // conv1
    conv_kernel<false><<<center_blocks, 128>>>(x, W1, nullptr, nullptr, h1);
    conv_kernel<true ><<<scat_grid,     128>>>(x, W1, in_map, out_map, h1);
    stats_kernel<<<2048, 256>>>(h1, 0);
    finalize_stats_kernel<<<1, 64>>>(gamma1, beta1, 0, 0);
    bnrelu_kernel<<<ew_blocks, 256>>>(h1, 0);

    // conv2
    conv_kernel<false><<<center_blocks, 128>>>(h1, W2, nullptr, nullptr, h2);
    conv_kernel<true ><<<scat_grid,     128>>>(h1, W2, in_map, out_map, h2);
    stats_kernel<<<2048, 256>>>(h2, 128);
    finalize_stats_kernel<<<1, 64>>>(gamma2, beta2, 128, 128);

    // bn2 + residual + relu -> d_out
    final_kernel<<<ew_blocks, 256>>>(h2, x, out, 128);
}